// round 4
// baseline (speedup 1.0000x reference)
#include <cuda_runtime.h>

// Twist2Mat (Rodrigues): twist [B,R,3] f32 -> rot [B,R,3,3] f32
// N = B*R = 8,388,608. Memory-bound: 384 MB streaming traffic.
//
// R1: strided per-thread stores -> 9x L1 wf amplification (166us).
// R2: block smem staging, coalesced I/O (66.3us, DRAM 68%).
// R3: warp-private tiles + __ldcs/__stcs (63.9us, DRAM 70%).
// R4: 4 tiles/warp with double-buffered prefetch: overlap next tile's DRAM
//     load latency with current tile's compute+store; grid 32768->8192.

#ifndef TPB
#define TPB 256
#endif
#define WARPS (TPB / 32)
#define TILES 4            // 32-element tiles per warp => 128 elems/warp

__device__ __forceinline__ void rodrigues9(float x, float y, float z, float* __restrict__ r)
{
    float n2    = fmaf(x, x, fmaf(y, y, z * z));
    float theta = fmaxf(sqrtf(n2), 1e-5f);
    float inv   = __fdividef(1.0f, theta);
    float a0 = x * inv, a1 = y * inv, a2 = z * inv;

    float s, c;
    __sincosf(theta, &s, &c);
    float k = 1.0f - c;

    // R = c*I + s*[a]_x + k*(a a^T)
    float ka0 = k * a0, ka1 = k * a1;
    float sa0 = s * a0, sa1 = s * a1, sa2 = s * a2;

    r[0] = fmaf(ka0, a0, c);
    r[1] = fmaf(ka0, a1, -sa2);
    r[2] = fmaf(ka0, a2,  sa1);
    r[3] = fmaf(ka0, a1,  sa2);
    r[4] = fmaf(ka1, a1, c);
    r[5] = fmaf(ka1, a2, -sa0);
    r[6] = fmaf(ka0, a2, -sa1);
    r[7] = fmaf(ka1, a2,  sa0);
    r[8] = fmaf(k * a2, a2, c);
}

// Per warp: TILES consecutive 32-element tiles.
//   tile in : 24 float4 (lanes 0..23), tile out: 72 float4.
// Double-buffered s_in; tile t+1 LDG issued before tile t compute/store.
__global__ __launch_bounds__(TPB)
void twist2mat_pipe_kernel(const float4* __restrict__ in4,
                           float4* __restrict__ out4,
                           int n_elems)
{
    __shared__ float s_in [WARPS][2][96];
    __shared__ float s_out[WARPS][288];

    const int lane = threadIdx.x & 31;
    const int wrp  = threadIdx.x >> 5;
    const long long wstart = ((long long)blockIdx.x * WARPS + wrp) * (32 * TILES);
    if (wstart >= n_elems) return;

    const float4* gin  = in4  + wstart / 4 * 3;   // wstart*3/4
    float4*       gout = out4 + wstart / 4 * 9;   // wstart*9/4

    // ---- preload tile 0 ----
    {
        long long t0 = wstart;
        if (t0 + 32 <= n_elems) {
            if (lane < 24)
                ((float4*)s_in[wrp][0])[lane] = __ldcs(gin + lane);
        } else {
            const float* gf = (const float*)gin;
            int vf = (int)(n_elems - t0) * 3;
            for (int i = lane; i < 96; i += 32)
                s_in[wrp][0][i] = (i < vf) ? gf[i] : 1.0f;
        }
    }

#pragma unroll
    for (int t = 0; t < TILES; t++) {
        const long long tbase = wstart + 32LL * t;
        if (tbase >= n_elems) break;

        // ---- prefetch tile t+1 into registers (overlaps with compute/store) ----
        float4 pf;
        const long long nbase = tbase + 32;
        const bool pf_full = (t + 1 < TILES) && (nbase + 32 <= n_elems);
        if (pf_full && lane < 24)
            pf = __ldcs(gin + (t + 1) * 24 + lane);

        __syncwarp();   // s_in[cur] visible to all lanes

        // ---- compute: 1 element per lane ----
        {
            const float* si = s_in[wrp][t & 1];
            float x = si[3 * lane + 0];
            float y = si[3 * lane + 1];
            float z = si[3 * lane + 2];
            float r[9];
            rodrigues9(x, y, z, r);
#pragma unroll
            for (int i = 0; i < 9; i++)
                s_out[wrp][9 * lane + i] = r[i];      // stride-9: conflict-free
        }
        __syncwarp();

        // ---- coalesced streaming store: 72 float4 ----
        if (tbase + 32 <= n_elems) {
            float4* go = gout + t * 72;
            const float4* so = (const float4*)s_out[wrp];
            __stcs(go + lane,      so[lane]);
            __stcs(go + lane + 32, so[lane + 32]);
            if (lane < 8) __stcs(go + lane + 64, so[lane + 64]);
        } else {
            float* gf = (float*)(gout + t * 72);
            int vf = (int)(n_elems - tbase) * 9;
            for (int i = lane; i < vf; i += 32)
                gf[i] = s_out[wrp][i];
        }

        // ---- commit prefetch to alt buffer (or slow-path load for partial next tile) ----
        if (t + 1 < TILES && nbase < n_elems) {
            if (pf_full) {
                if (lane < 24)
                    ((float4*)s_in[wrp][(t + 1) & 1])[lane] = pf;
            } else {
                const float* gf = (const float*)(gin + (t + 1) * 24);
                int vf = (int)(n_elems - nbase) * 3;
                for (int i = lane; i < 96; i += 32)
                    s_in[wrp][(t + 1) & 1][i] = (i < vf) ? gf[i] : 1.0f;
            }
        }
        // next iteration's leading __syncwarp orders these STS before the reads
    }
}

extern "C" void kernel_launch(void* const* d_in, const int* in_sizes, int n_in,
                              void* d_out, int out_size)
{
    const float* twist = (const float*)d_in[0];
    float* out = (float*)d_out;

    int n_elems = in_sizes[0] / 3;                       // 8,388,608
    long long per_block = (long long)WARPS * 32 * TILES; // 1024
    int blocks = (int)((n_elems + per_block - 1) / per_block);

    twist2mat_pipe_kernel<<<blocks, TPB>>>((const float4*)twist, (float4*)out, n_elems);
}

// round 5
// speedup vs baseline: 1.0204x; 1.0204x over previous
#include <cuda_runtime.h>

// Twist2Mat (Rodrigues): twist [B,R,3] f32 -> rot [B,R,3,3] f32
// N = B*R = 8,388,608. Memory-bound: 384 MB streaming traffic.
//
// R1: strided per-thread stores -> 9x L1 wf amplification (166us).
// R2: block smem staging, coalesced I/O (66.3us, DRAM 68%).
// R3: warp-private tiles + __ldcs/__stcs (63.9us, DRAM 70%).
// R4: 1-deep register prefetch — marginal (DRAM 71.9%, wallclock regressed).
// R5: batch ALL warp loads up front (3 independent LDG.128 per lane) to
//     triple in-flight read bytes per SM (latency-BW product fix).

#ifndef TPB
#define TPB 256
#endif
#define WARPS (TPB / 32)
#define TILES 4            // 32-element tiles per warp => 128 elems/warp

__device__ __forceinline__ void rodrigues9(float x, float y, float z, float* __restrict__ r)
{
    float n2    = fmaf(x, x, fmaf(y, y, z * z));
    float theta = fmaxf(sqrtf(n2), 1e-5f);
    float inv   = __fdividef(1.0f, theta);
    float a0 = x * inv, a1 = y * inv, a2 = z * inv;

    float s, c;
    __sincosf(theta, &s, &c);
    float k = 1.0f - c;

    // R = c*I + s*[a]_x + k*(a a^T)
    float ka0 = k * a0, ka1 = k * a1;
    float sa0 = s * a0, sa1 = s * a1, sa2 = s * a2;

    r[0] = fmaf(ka0, a0, c);
    r[1] = fmaf(ka0, a1, -sa2);
    r[2] = fmaf(ka0, a2,  sa1);
    r[3] = fmaf(ka0, a1,  sa2);
    r[4] = fmaf(ka1, a1, c);
    r[5] = fmaf(ka1, a2, -sa0);
    r[6] = fmaf(ka0, a2, -sa1);
    r[7] = fmaf(ka1, a2,  sa0);
    r[8] = fmaf(k * a2, a2, c);
}

// Per warp: 128 contiguous elements.
//   in : 128*3 floats = 96 float4  -> 3 independent LDG.128 per lane, batched
//   out: per 32-elem tile, 72 float4 coalesced streaming stores
__global__ __launch_bounds__(TPB)
void twist2mat_mlp_kernel(const float4* __restrict__ in4,
                          float4* __restrict__ out4,
                          int n_elems)
{
    __shared__ float s_in [WARPS][TILES * 96];   // 1536 B / warp
    __shared__ float s_out[WARPS][288];          // 1152 B / warp

    const int lane = threadIdx.x & 31;
    const int wrp  = threadIdx.x >> 5;
    const long long wstart = ((long long)blockIdx.x * WARPS + wrp) * (32 * TILES);
    if (wstart >= n_elems) return;

    const float4* gin  = in4  + wstart / 4 * 3;   // wstart*3/4
    float4*       gout = out4 + wstart / 4 * 9;   // wstart*9/4

    const bool warp_full = (wstart + 32 * TILES <= n_elems);

    // ---- batched load: 96 float4 per warp, 3 independent per lane ----
    if (warp_full) {
        float4* s = (float4*)s_in[wrp];
#pragma unroll
        for (int j = 0; j < 3; j++)
            s[lane + 32 * j] = __ldcs(gin + lane + 32 * j);
    } else {
        const float* gf = (const float*)gin;
        int vf = (int)(n_elems - wstart) * 3;
        for (int i = lane; i < TILES * 96; i += 32)
            s_in[wrp][i] = (i < vf) ? gf[i] : 1.0f;   // pad, never stored
    }
    __syncwarp();

#pragma unroll
    for (int t = 0; t < TILES; t++) {
        const long long tbase = wstart + 32LL * t;
        if (tbase >= n_elems) break;

        // ---- compute: 1 element per lane (stride-3 LDS: conflict-free) ----
        {
            const float* si = s_in[wrp] + t * 96;
            float x = si[3 * lane + 0];
            float y = si[3 * lane + 1];
            float z = si[3 * lane + 2];
            float r[9];
            rodrigues9(x, y, z, r);
#pragma unroll
            for (int i = 0; i < 9; i++)
                s_out[wrp][9 * lane + i] = r[i];      // stride-9 STS: conflict-free
        }
        __syncwarp();

        // ---- coalesced streaming store: 72 float4 ----
        if (tbase + 32 <= n_elems) {
            float4* go = gout + t * 72;
            const float4* so = (const float4*)s_out[wrp];
            __stcs(go + lane,      so[lane]);
            __stcs(go + lane + 32, so[lane + 32]);
            if (lane < 8) __stcs(go + lane + 64, so[lane + 64]);
        } else {
            float* gf = (float*)(gout + t * 72);
            int vf = (int)(n_elems - tbase) * 9;
            for (int i = lane; i < vf; i += 32)
                gf[i] = s_out[wrp][i];
        }
        __syncwarp();   // s_out reused next tile: order stores before overwrite
    }
}

extern "C" void kernel_launch(void* const* d_in, const int* in_sizes, int n_in,
                              void* d_out, int out_size)
{
    const float* twist = (const float*)d_in[0];
    float* out = (float*)d_out;

    int n_elems = in_sizes[0] / 3;                       // 8,388,608
    long long per_block = (long long)WARPS * 32 * TILES; // 1024
    int blocks = (int)((n_elems + per_block - 1) / per_block);

    twist2mat_mlp_kernel<<<blocks, TPB>>>((const float4*)twist, (float4*)out, n_elems);
}

// round 6
// speedup vs baseline: 1.0260x; 1.0055x over previous
#include <cuda_runtime.h>
#include <cstdint>

// Twist2Mat (Rodrigues): twist [B,R,3] f32 -> rot [B,R,3,3] f32
// N = B*R = 8,388,608. Memory-bound: 384 MB streaming (96 read / 288 write).
//
// R1: strided per-thread stores -> 9x L1 wf amplification (166us).
// R2: block smem staging, coalesced I/O (66.3us, DRAM 68%).
// R3: warp-private tiles + __ldcs/__stcs (63.9us, DRAM 70%).
// R4: 1-deep register prefetch — neutral.
// R5: batched read MLP (3 LDG.128/lane) — neutral: reads not the constraint.
// R6: TMA bulk stores (cp.async.bulk shared->global, 1152B per tile-warp),
//     double-buffered s_out. Store path leaves L1tex/LSU entirely.

#ifndef TPB
#define TPB 256
#endif
#define WARPS (TPB / 32)
#define TILES 4            // 32-element tiles per warp => 128 elems/warp

__device__ __forceinline__ void rodrigues9(float x, float y, float z, float* __restrict__ r)
{
    float n2    = fmaf(x, x, fmaf(y, y, z * z));
    float theta = fmaxf(sqrtf(n2), 1e-5f);
    float inv   = __fdividef(1.0f, theta);
    float a0 = x * inv, a1 = y * inv, a2 = z * inv;

    float s, c;
    __sincosf(theta, &s, &c);
    float k = 1.0f - c;

    // R = c*I + s*[a]_x + k*(a a^T)
    float ka0 = k * a0, ka1 = k * a1;
    float sa0 = s * a0, sa1 = s * a1, sa2 = s * a2;

    r[0] = fmaf(ka0, a0, c);
    r[1] = fmaf(ka0, a1, -sa2);
    r[2] = fmaf(ka0, a2,  sa1);
    r[3] = fmaf(ka0, a1,  sa2);
    r[4] = fmaf(ka1, a1, c);
    r[5] = fmaf(ka1, a2, -sa0);
    r[6] = fmaf(ka0, a2, -sa1);
    r[7] = fmaf(ka1, a2,  sa0);
    r[8] = fmaf(k * a2, a2, c);
}

__global__ __launch_bounds__(TPB)
void twist2mat_tma_kernel(const float4* __restrict__ in4,
                          float4* __restrict__ out4,
                          int n_elems)
{
    __shared__ float s_in [WARPS][TILES * 96];                      // 1536 B / warp
    __shared__ __align__(16) float s_out[WARPS][2][288];            // 2x1152 B / warp

    const int lane = threadIdx.x & 31;
    const int wrp  = threadIdx.x >> 5;
    const long long wstart = ((long long)blockIdx.x * WARPS + wrp) * (32 * TILES);
    if (wstart >= n_elems) return;

    const float4* gin  = in4  + wstart / 4 * 3;   // wstart*3/4
    float4*       gout = out4 + wstart / 4 * 9;   // wstart*9/4

    const bool warp_full = (wstart + 32 * TILES <= n_elems);

    // ---- batched coalesced load: 96 float4 per warp (3 per lane) ----
    if (warp_full) {
        float4* s = (float4*)s_in[wrp];
#pragma unroll
        for (int j = 0; j < 3; j++)
            s[lane + 32 * j] = __ldcs(gin + lane + 32 * j);
    } else {
        const float* gf = (const float*)gin;
        int vf = (int)(n_elems - wstart) * 3;
        for (int i = lane; i < TILES * 96; i += 32)
            s_in[wrp][i] = (i < vf) ? gf[i] : 1.0f;   // pad, never stored
    }
    __syncwarp();

    if (warp_full) {
#pragma unroll
        for (int t = 0; t < TILES; t++) {
            // Before reusing buffer (t&1), the bulk store issued at tile t-2
            // must have finished READING it. Groups retire in order, so
            // "at most 1 pending" => group t-2's smem reads are done.
            if (t >= 2) {
                if (lane == 0)
                    asm volatile("cp.async.bulk.wait_group.read 1;" ::: "memory");
                __syncwarp();
            }

            // ---- compute: 1 element per lane ----
            {
                const float* si = s_in[wrp] + t * 96;
                float x = si[3 * lane + 0];
                float y = si[3 * lane + 1];
                float z = si[3 * lane + 2];
                float r[9];
                rodrigues9(x, y, z, r);
                float* so = s_out[wrp][t & 1];
#pragma unroll
                for (int i = 0; i < 9; i++)
                    so[9 * lane + i] = r[i];          // stride-9 STS: conflict-free
            }
            __syncwarp();

            // ---- TMA bulk store: 1152 contiguous bytes, async proxy ----
            if (lane == 0) {
                asm volatile("fence.proxy.async.shared::cta;" ::: "memory");
                uint32_t src = (uint32_t)__cvta_generic_to_shared(s_out[wrp][t & 1]);
                void* dst = (void*)(gout + t * 72);
                asm volatile(
                    "cp.async.bulk.global.shared::cta.bulk_group [%0], [%1], %2;"
                    :: "l"(dst), "r"(src), "n"(1152) : "memory");
                asm volatile("cp.async.bulk.commit_group;" ::: "memory");
            }
        }
        // Drain all bulk stores before this warp exits.
        if (lane == 0)
            asm volatile("cp.async.bulk.wait_group 0;" ::: "memory");
    } else {
        // ---- scalar-safe tail path (not hit for this shape) ----
        for (int t = 0; t < TILES; t++) {
            const long long tbase = wstart + 32LL * t;
            if (tbase >= n_elems) break;
            const float* si = s_in[wrp] + t * 96;
            float r[9];
            rodrigues9(si[3 * lane], si[3 * lane + 1], si[3 * lane + 2], r);
            float* so = s_out[wrp][0];
#pragma unroll
            for (int i = 0; i < 9; i++)
                so[9 * lane + i] = r[i];
            __syncwarp();
            float* gf = (float*)(gout + t * 72);
            long long ve = n_elems - tbase;
            int vf = (int)((ve < 32 ? ve : 32) * 9);
            for (int i = lane; i < vf; i += 32)
                gf[i] = so[i];
            __syncwarp();
        }
    }
}

extern "C" void kernel_launch(void* const* d_in, const int* in_sizes, int n_in,
                              void* d_out, int out_size)
{
    const float* twist = (const float*)d_in[0];
    float* out = (float*)d_out;

    int n_elems = in_sizes[0] / 3;                       // 8,388,608
    long long per_block = (long long)WARPS * 32 * TILES; // 1024
    int blocks = (int)((n_elems + per_block - 1) / per_block);

    twist2mat_tma_kernel<<<blocks, TPB>>>((const float4*)twist, (float4*)out, n_elems);
}